// round 11
// baseline (speedup 1.0000x reference)
#include <cuda_runtime.h>
#include <math.h>
#include <stdint.h>

typedef unsigned long long ull;

#define BATCH 64
#define SEQ   2048
#define IN_F  256
#define HID   512
#define RANKS 8     // CTAs per cluster; each owns 64 columns of W_hh
#define BPC   4     // batch rows per cluster

#define REGION_BYTES 1152          // 64 entries x 16B + 8 dup-pad entries
#define BUF_BYTES    (RANKS * REGION_BYTES)

// ---------------------------------------------------------------------------
// Packed f32x2 helpers
// ---------------------------------------------------------------------------
__device__ __forceinline__ ull ffma2(ull a, ull b, ull c) {
    ull d;
    asm("fma.rn.f32x2 %0, %1, %2, %3;" : "=l"(d) : "l"(a), "l"(b), "l"(c));
    return d;
}
__device__ __forceinline__ ull addx2(ull a, ull b) {
    ull d;
    asm("add.rn.f32x2 %0, %1, %2;" : "=l"(d) : "l"(a), "l"(b));
    return d;
}
__device__ __forceinline__ ull dup2(float x) {
    ull d;
    asm("mov.b64 %0, {%1, %1};" : "=l"(d) : "f"(x));
    return d;
}
__device__ __forceinline__ ull pack2(float lo, float hi) {
    ull d;
    asm("mov.b64 %0, {%1, %2};" : "=l"(d) : "f"(lo), "f"(hi));
    return d;
}
__device__ __forceinline__ float f2lo(ull v) {
    return __int_as_float((int)(unsigned int)(v & 0xffffffffULL));
}
__device__ __forceinline__ float f2hi(ull v) {
    return __int_as_float((int)(unsigned int)(v >> 32));
}

// ---------------------------------------------------------------------------
// mbarrier / cluster primitives
// ---------------------------------------------------------------------------
__device__ __forceinline__ void mbar_init(uint32_t mbar, uint32_t cnt) {
    asm volatile("mbarrier.init.shared.b64 [%0], %1;" :: "r"(mbar), "r"(cnt) : "memory");
}
// cluster-scope acquire wait with suspend hint (R6-style sleep path)
__device__ __forceinline__ void mbar_wait_cl(uint32_t mbar, uint32_t parity) {
    asm volatile(
        "{\n\t"
        ".reg .pred P;\n\t"
        "WL_%=:\n\t"
        "mbarrier.try_wait.parity.acquire.cluster.shared::cta.b64 P, [%0], %1, 0x989680;\n\t"
        "@P bra.uni WD_%=;\n\t"
        "bra.uni WL_%=;\n\t"
        "WD_%=:\n\t"
        "}"
        :: "r"(mbar), "r"(parity) : "memory");
}
// direct remote store: write u64 to same smem offset in cluster CTA r
__device__ __forceinline__ void st_cluster_u64(uint32_t saddr, int r, ull v) {
    uint32_t ra;
    asm volatile("mapa.shared::cluster.u32 %0, %1, %2;" : "=r"(ra) : "r"(saddr), "r"(r));
    asm volatile("st.shared::cluster.u64 [%0], %1;" :: "r"(ra), "l"(v) : "memory");
}
// release-arrive on peer r's mbarrier (same smem offset)
__device__ __forceinline__ void mbar_arrive_remote(uint32_t local_mbar, int r) {
    uint32_t rm;
    asm volatile("mapa.shared::cluster.u32 %0, %1, %2;" : "=r"(rm) : "r"(local_mbar), "r"(r));
    asm volatile("mbarrier.arrive.release.cluster.shared::cluster.b64 _, [%0];"
                 :: "r"(rm) : "memory");
}
__device__ __forceinline__ void cluster_sync_() {
    asm volatile("barrier.cluster.arrive.aligned;" ::: "memory");
    asm volatile("barrier.cluster.wait.aligned;" ::: "memory");
}

// ---------------------------------------------------------------------------
// Kernel 1: x_proj GEMM  out[m][n] = sum_k X[m][k]*Wih[n][k] + bih[n] + bhh[n]
// ---------------------------------------------------------------------------
#define BM 128
#define BN 64
#define BK 32
#define ASP 130

__global__ __launch_bounds__(256) void xproj_kernel(
    const float* __restrict__ X, const float* __restrict__ Wih,
    const float* __restrict__ bih, const float* __restrict__ bhh,
    float* __restrict__ out)
{
    __shared__ float As[BK][ASP];
    __shared__ float Ws[BK][BN];

    const int tid = threadIdx.x;
    const int m0 = blockIdx.x * BM;
    const int n0 = blockIdx.y * BN;
    const int tx = tid & 15;
    const int ty = tid >> 4;

    ull acc[4][4];
#pragma unroll
    for (int r = 0; r < 4; r++)
#pragma unroll
        for (int c = 0; c < 4; c++) acc[r][c] = 0ULL;

    for (int k0 = 0; k0 < IN_F; k0 += BK) {
#pragma unroll
        for (int i = 0; i < 4; i++) {
            int idx = tid + i * 256;
            int m = idx >> 3;
            int k4 = idx & 7;
            float4 v = *(const float4*)(X + (size_t)(m0 + m) * IN_F + k0 + k4 * 4);
            As[k4 * 4 + 0][m] = v.x;
            As[k4 * 4 + 1][m] = v.y;
            As[k4 * 4 + 2][m] = v.z;
            As[k4 * 4 + 3][m] = v.w;
        }
#pragma unroll
        for (int i = 0; i < 2; i++) {
            int idx = tid + i * 256;
            int n = idx >> 3;
            int k4 = idx & 7;
            float4 v = *(const float4*)(Wih + (size_t)(n0 + n) * IN_F + k0 + k4 * 4);
            Ws[k4 * 4 + 0][n] = v.x;
            Ws[k4 * 4 + 1][n] = v.y;
            Ws[k4 * 4 + 2][n] = v.z;
            Ws[k4 * 4 + 3][n] = v.w;
        }
        __syncthreads();

#pragma unroll
        for (int k = 0; k < BK; k++) {
            ull ap[4];
#pragma unroll
            for (int r = 0; r < 4; r++)
                ap[r] = *(const ull*)&As[k][ty * 8 + 2 * r];
            float4 wv = *(const float4*)&Ws[k][tx * 4];
            ull wd0 = dup2(wv.x), wd1 = dup2(wv.y);
            ull wd2 = dup2(wv.z), wd3 = dup2(wv.w);
#pragma unroll
            for (int r = 0; r < 4; r++) {
                acc[r][0] = ffma2(ap[r], wd0, acc[r][0]);
                acc[r][1] = ffma2(ap[r], wd1, acc[r][1]);
                acc[r][2] = ffma2(ap[r], wd2, acc[r][2]);
                acc[r][3] = ffma2(ap[r], wd3, acc[r][3]);
            }
        }
        __syncthreads();
    }

    float bsum[4];
#pragma unroll
    for (int c = 0; c < 4; c++) {
        int n = n0 + tx * 4 + c;
        bsum[c] = bih[n] + bhh[n];
    }
#pragma unroll
    for (int r = 0; r < 4; r++) {
        size_t mlo = (size_t)(m0 + ty * 8 + 2 * r);
        float4 lo4, hi4;
        lo4.x = f2lo(acc[r][0]) + bsum[0]; lo4.y = f2lo(acc[r][1]) + bsum[1];
        lo4.z = f2lo(acc[r][2]) + bsum[2]; lo4.w = f2lo(acc[r][3]) + bsum[3];
        hi4.x = f2hi(acc[r][0]) + bsum[0]; hi4.y = f2hi(acc[r][1]) + bsum[1];
        hi4.z = f2hi(acc[r][2]) + bsum[2]; hi4.w = f2hi(acc[r][3]) + bsum[3];
        *(float4*)(out + mlo * HID + n0 + tx * 4)       = lo4;
        *(float4*)(out + (mlo + 1) * HID + n0 + tx * 4) = hi4;
    }
}

// ---------------------------------------------------------------------------
// Kernel 2: cluster scan — R6 skeleton (single mbar wait + single syncthreads
// per step, rotated conflict-free layout) with DIRECT-STORE transport:
// writers push their 8B entries straight into all 7 peers' next buffer
// (st.shared::cluster), and tid0 signals each peer with ONE release-arrive
// after __syncthreads (mbar count = 7, one arrive per sending CTA).
// No bulk-DMA engine on the critical path.
//
// 16 clusters x 8 CTAs; cluster owns 4 batch rows, CTA rank owns 64 cols.
// 512 threads: col = tid>>3 (output column), kq = tid&7 (k-chunk of 64 =
// source region kq). W regs rotated: w[j] = Whh[gcol][kq*64 + ((j+kq)&63)]
// so lane kq reads region kq entries (kq+j) -> conflict-free LDS.128.
//
// h smem: 2 buffers x 8 regions x 72 entries x 16B; entry c of region r =
// ((h_b0,h_b1),(h_b2,h_b3)) for k = r*64+c; entries 64..71 duplicate 0..7.
//
// Memory-model chain per step: writer lanes' weak cluster-stores
//  -> __syncthreads (CTA hb) -> tid0 fence.acq_rel.cluster
//  -> tid0 mbarrier.arrive.release.cluster on peer
//  -> peer's try_wait acquire.cluster -> peer's LDS reads.
// ---------------------------------------------------------------------------
__global__ void __cluster_dims__(RANKS, 1, 1) __launch_bounds__(512, 1)
scan_kernel(const float* __restrict__ h0, const float* __restrict__ Whh,
            float* __restrict__ out)
{
    __shared__ __align__(16) char hpraw[2 * BUF_BYTES];
    __shared__ __align__(8) ull mbars[2];

    const int tid  = threadIdx.x;
    const int kq   = tid & 7;
    const int col  = tid >> 3;                 // 0..63
    const int rank = blockIdx.x & (RANKS - 1);
    const int cid  = blockIdx.x >> 3;
    const int b0   = cid * BPC;
    const int gcol = rank * 64 + col;

    // ---- W slice, rotated load (one-time)
    float w[64];
    {
        const float* wrow = Whh + (size_t)gcol * HID + kq * 64;
#pragma unroll
        for (int j = 0; j < 64; j++)
            w[j] = wrow[(j + kq) & 63];
    }

    if (tid == 0) {
        mbar_init((uint32_t)__cvta_generic_to_shared(&mbars[0]), 7);
        mbar_init((uint32_t)__cvta_generic_to_shared(&mbars[1]), 7);
    }

    // ---- preload h0 into buffer 0 (each CTA loads full h for its 4 rows)
    {
        const int k = tid;                     // 512 threads, one k each
        float v0 = h0[(size_t)(b0 + 0) * HID + k];
        float v1 = h0[(size_t)(b0 + 1) * HID + k];
        float v2 = h0[(size_t)(b0 + 2) * HID + k];
        float v3 = h0[(size_t)(b0 + 3) * HID + k];
        ull lo = pack2(v0, v1), hi = pack2(v2, v3);
        int r = k >> 6, c = k & 63;
        char* e = hpraw + r * REGION_BYTES + c * 16;
        *(ull*)e = lo;
        *(ull*)(e + 8) = hi;
        if (c < 8) {                            // duplication pad
            *(ull*)(e + 1024) = lo;
            *(ull*)(e + 1024 + 8) = hi;
        }
    }
    __syncthreads();
    cluster_sync_();            // mbar inits + buffer0 visible cluster-wide

    const uint32_t hpb = (uint32_t)__cvta_generic_to_shared(hpraw);
    const uint32_t mbb = (uint32_t)__cvta_generic_to_shared(&mbars[0]);

    const bool outlane = (kq < 4);
    const size_t obase = outlane ? (((size_t)(b0 + kq) * SEQ) * HID + gcol) : 0;
    float xpv = outlane ? out[obase] : 0.0f;

    const bool writer = (kq == 0) || (kq == 2);

    for (int t = 0; t < SEQ; t++) {
        const int p = t & 1;
        if (t) mbar_wait_cl(mbb + p * 8, ((t - 1) >> 1) & 1);

        // region of source rank kq, rotated start
        const ulonglong2* hreg =
            (const ulonglong2*)(hpraw + p * BUF_BYTES + kq * REGION_BYTES) + kq;
        ull a01 = 0, a23 = 0;
#pragma unroll
        for (int j = 0; j < 64; j++) {
            ulonglong2 h2 = hreg[j];
            ull wd = dup2(w[j]);
            a01 = ffma2(wd, h2.x, a01);
            a23 = ffma2(wd, h2.y, a23);
        }

        // prefetch next step's xp while reduction/exchange runs
        float xpn = 0.0f;
        if (outlane && t + 1 < SEQ) xpn = out[obase + (size_t)(t + 1) * HID];

        // allreduce partial sums across the 8 kq lanes
#pragma unroll
        for (int m = 1; m < 8; m <<= 1) {
            a01 = addx2(a01, __shfl_xor_sync(0xffffffffu, a01, m));
            a23 = addx2(a23, __shfl_xor_sync(0xffffffffu, a23, m));
        }

        // this lane's output value
        float v = 0.0f;
        if (outlane) {
            ull ap = (kq < 2) ? a01 : a23;
            float s = (kq & 1) ? f2hi(ap) : f2lo(ap);
            v = tanhf(s + xpv);
        }
        xpv = xpn;

        // pair partner (same col, next batch of the pair)
        float vn = __shfl_down_sync(0xffffffffu, v, 1);

        if (t < SEQ - 1 && writer) {
            const ull pk = pack2(v, vn);
            const uint32_t eoff =
                (uint32_t)((1 - p) * BUF_BYTES + rank * REGION_BYTES +
                           col * 16 + ((kq & 2) << 2));
            // local copy (+ dup pad)
            *(ull*)(hpraw + eoff) = pk;
            if (col < 8) *(ull*)(hpraw + eoff + 1024) = pk;
            // direct push to all 7 peers (fire-and-forget DSMEM stores)
            const uint32_t loff = hpb + eoff;
#pragma unroll
            for (int d = 1; d < RANKS; d++) {
                const int dst = (rank + d) & (RANKS - 1);
                st_cluster_u64(loff, dst, pk);
                if (col < 8) st_cluster_u64(loff + 1024, dst, pk);
            }
        }

        __syncthreads();   // closes all reads of buf p, orders all stores

        if (t < SEQ - 1 && tid == 0) {
            asm volatile("fence.acq_rel.cluster;" ::: "memory");
            const uint32_t lmb = mbb + (uint32_t)((1 - p) * 8);
#pragma unroll
            for (int d = 1; d < RANKS; d++)
                mbar_arrive_remote(lmb, (rank + d) & (RANKS - 1));
        }

        // output store off the signaling path
        if (outlane) out[obase + (size_t)t * HID] = v;
    }

    cluster_sync_();
}

// ---------------------------------------------------------------------------
// Launch
// ---------------------------------------------------------------------------
extern "C" void kernel_launch(void* const* d_in, const int* in_sizes, int n_in,
                              void* d_out, int out_size) {
    const float* x_in = (const float*)d_in[0];
    const float* h0   = (const float*)d_in[1];
    const float* W_ih = (const float*)d_in[2];
    const float* W_hh = (const float*)d_in[3];
    const float* b_ih = (const float*)d_in[4];
    const float* b_hh = (const float*)d_in[5];
    float* out = (float*)d_out;

    dim3 gg((BATCH * SEQ) / BM, HID / BN);
    xproj_kernel<<<gg, 256>>>(x_in, W_ih, b_ih, b_hh, out);

    scan_kernel<<<(BATCH / BPC) * RANKS, 512>>>(h0, W_hh, out);
}

// round 12
// speedup vs baseline: 2.2307x; 2.2307x over previous
#include <cuda_runtime.h>
#include <math.h>
#include <stdint.h>

typedef unsigned long long ull;

#define BATCH 64
#define SEQ   2048
#define IN_F  256
#define HID   512
#define RANKS 8     // CTAs per cluster; each owns 64 columns of W_hh
#define BPC   4     // batch rows per cluster

// 16 regions (one per kq lane) x 32 entries x 16B payload, stride 528 so the
// 16 lanes' concurrent reads spread over all banks (perfect 2-phase LDS).
#define REG_PAY   512
#define REG_STR   528
#define BUF_B     (16 * REG_STR)        // 8448 per buffer
#define CHUNK_B   1040                  // one rank's 2 regions (512+16+512)
#define EXCH_TX   (7 * CHUNK_B)         // 7280 incoming bytes per step

// ---------------------------------------------------------------------------
// Packed f32x2 helpers
// ---------------------------------------------------------------------------
__device__ __forceinline__ ull ffma2(ull a, ull b, ull c) {
    ull d;
    asm("fma.rn.f32x2 %0, %1, %2, %3;" : "=l"(d) : "l"(a), "l"(b), "l"(c));
    return d;
}
__device__ __forceinline__ ull addx2(ull a, ull b) {
    ull d;
    asm("add.rn.f32x2 %0, %1, %2;" : "=l"(d) : "l"(a), "l"(b));
    return d;
}
__device__ __forceinline__ ull dup2(float x) {
    ull d;
    asm("mov.b64 %0, {%1, %1};" : "=l"(d) : "f"(x));
    return d;
}
__device__ __forceinline__ ull pack2(float lo, float hi) {
    ull d;
    asm("mov.b64 %0, {%1, %2};" : "=l"(d) : "f"(lo), "f"(hi));
    return d;
}
__device__ __forceinline__ float f2lo(ull v) {
    return __int_as_float((int)(unsigned int)(v & 0xffffffffULL));
}
__device__ __forceinline__ float f2hi(ull v) {
    return __int_as_float((int)(unsigned int)(v >> 32));
}

// ---------------------------------------------------------------------------
// mbarrier / cluster primitives (R6-identical)
// ---------------------------------------------------------------------------
__device__ __forceinline__ void mbar_init(uint32_t mbar, uint32_t cnt) {
    asm volatile("mbarrier.init.shared.b64 [%0], %1;" :: "r"(mbar), "r"(cnt) : "memory");
}
__device__ __forceinline__ void mbar_expect_tx(uint32_t mbar, uint32_t bytes) {
    asm volatile("mbarrier.arrive.expect_tx.shared.b64 _, [%0], %1;"
                 :: "r"(mbar), "r"(bytes) : "memory");
}
__device__ __forceinline__ void mbar_wait(uint32_t mbar, uint32_t parity) {
    asm volatile(
        "{\n\t"
        ".reg .pred P;\n\t"
        "WL_%=:\n\t"
        "mbarrier.try_wait.parity.acquire.cta.shared::cta.b64 P, [%0], %1, 0x989680;\n\t"
        "@P bra.uni WD_%=;\n\t"
        "bra.uni WL_%=;\n\t"
        "WD_%=:\n\t"
        "}"
        :: "r"(mbar), "r"(parity) : "memory");
}
// bulk copy: our smem chunk -> same offset in cluster rank r, signal r's mbar
__device__ __forceinline__ void cluster_bulk_copy(uint32_t local_addr, uint32_t bytes,
                                                  uint32_t local_mbar, int r) {
    uint32_t rdst, rmb;
    asm volatile("mapa.shared::cluster.u32 %0, %1, %2;" : "=r"(rdst) : "r"(local_addr), "r"(r));
    asm volatile("mapa.shared::cluster.u32 %0, %1, %2;" : "=r"(rmb) : "r"(local_mbar), "r"(r));
    asm volatile(
        "cp.async.bulk.shared::cluster.shared::cta.mbarrier::complete_tx::bytes "
        "[%0], [%1], %2, [%3];"
        :: "r"(rdst), "r"(local_addr), "r"(bytes), "r"(rmb) : "memory");
}
__device__ __forceinline__ void cluster_sync_() {
    asm volatile("barrier.cluster.arrive.aligned;" ::: "memory");
    asm volatile("barrier.cluster.wait.aligned;" ::: "memory");
}

// ---------------------------------------------------------------------------
// Kernel 1: x_proj GEMM  out[m][n] = sum_k X[m][k]*Wih[n][k] + bih[n] + bhh[n]
// ---------------------------------------------------------------------------
#define BM 128
#define BN 64
#define BK 32
#define ASP 130

__global__ __launch_bounds__(256) void xproj_kernel(
    const float* __restrict__ X, const float* __restrict__ Wih,
    const float* __restrict__ bih, const float* __restrict__ bhh,
    float* __restrict__ out)
{
    __shared__ float As[BK][ASP];
    __shared__ float Ws[BK][BN];

    const int tid = threadIdx.x;
    const int m0 = blockIdx.x * BM;
    const int n0 = blockIdx.y * BN;
    const int tx = tid & 15;
    const int ty = tid >> 4;

    ull acc[4][4];
#pragma unroll
    for (int r = 0; r < 4; r++)
#pragma unroll
        for (int c = 0; c < 4; c++) acc[r][c] = 0ULL;

    for (int k0 = 0; k0 < IN_F; k0 += BK) {
#pragma unroll
        for (int i = 0; i < 4; i++) {
            int idx = tid + i * 256;
            int m = idx >> 3;
            int k4 = idx & 7;
            float4 v = *(const float4*)(X + (size_t)(m0 + m) * IN_F + k0 + k4 * 4);
            As[k4 * 4 + 0][m] = v.x;
            As[k4 * 4 + 1][m] = v.y;
            As[k4 * 4 + 2][m] = v.z;
            As[k4 * 4 + 3][m] = v.w;
        }
#pragma unroll
        for (int i = 0; i < 2; i++) {
            int idx = tid + i * 256;
            int n = idx >> 3;
            int k4 = idx & 7;
            float4 v = *(const float4*)(Wih + (size_t)(n0 + n) * IN_F + k0 + k4 * 4);
            Ws[k4 * 4 + 0][n] = v.x;
            Ws[k4 * 4 + 1][n] = v.y;
            Ws[k4 * 4 + 2][n] = v.z;
            Ws[k4 * 4 + 3][n] = v.w;
        }
        __syncthreads();

#pragma unroll
        for (int k = 0; k < BK; k++) {
            ull ap[4];
#pragma unroll
            for (int r = 0; r < 4; r++)
                ap[r] = *(const ull*)&As[k][ty * 8 + 2 * r];
            float4 wv = *(const float4*)&Ws[k][tx * 4];
            ull wd0 = dup2(wv.x), wd1 = dup2(wv.y);
            ull wd2 = dup2(wv.z), wd3 = dup2(wv.w);
#pragma unroll
            for (int r = 0; r < 4; r++) {
                acc[r][0] = ffma2(ap[r], wd0, acc[r][0]);
                acc[r][1] = ffma2(ap[r], wd1, acc[r][1]);
                acc[r][2] = ffma2(ap[r], wd2, acc[r][2]);
                acc[r][3] = ffma2(ap[r], wd3, acc[r][3]);
            }
        }
        __syncthreads();
    }

    float bsum[4];
#pragma unroll
    for (int c = 0; c < 4; c++) {
        int n = n0 + tx * 4 + c;
        bsum[c] = bih[n] + bhh[n];
    }
#pragma unroll
    for (int r = 0; r < 4; r++) {
        size_t mlo = (size_t)(m0 + ty * 8 + 2 * r);
        float4 lo4, hi4;
        lo4.x = f2lo(acc[r][0]) + bsum[0]; lo4.y = f2lo(acc[r][1]) + bsum[1];
        lo4.z = f2lo(acc[r][2]) + bsum[2]; lo4.w = f2lo(acc[r][3]) + bsum[3];
        hi4.x = f2hi(acc[r][0]) + bsum[0]; hi4.y = f2hi(acc[r][1]) + bsum[1];
        hi4.z = f2hi(acc[r][2]) + bsum[2]; hi4.w = f2hi(acc[r][3]) + bsum[3];
        *(float4*)(out + mlo * HID + n0 + tx * 4)       = lo4;
        *(float4*)(out + (mlo + 1) * HID + n0 + tx * 4) = hi4;
    }
}

// ---------------------------------------------------------------------------
// Kernel 2: cluster scan — EXACT R6 exchange protocol (single mbar per
// buffer; tid0: expect_tx -> __syncthreads -> fence -> 7 bulk copies), but
// compute remapped to 2 columns/thread to HALVE smem crossbar traffic.
//
// 16 clusters x 8 CTAs; cluster owns 4 batch rows, CTA rank owns 64 cols.
// 512 threads: g = tid>>4 in [0,32) owns cols {2g, 2g+1}; kq = tid&15 is the
// k-chunk [32kq, 32kq+32).
//
// h smem: 2 buffers x 16 regions x 32 entries x 16B (stride 528). Entry c of
// region r = ((h_b0,h_b1),(h_b2,h_b3)) for k = r*32+c. A warp's 16 kq-lanes
// read addresses (16*(kq mod 8) + 16c) mod 128 -> every bank exactly twice =
// optimal 2-phase LDS.128. Per entry each thread does 8 MACs (2 cols x 4 b).
//
// Rank r owns regions {2r, 2r+1}; its exchange chunk is the contiguous
// 1040B [2r*528, 2r*528+1040) covering both regions' payloads.
// ---------------------------------------------------------------------------
__global__ void __cluster_dims__(RANKS, 1, 1) __launch_bounds__(512, 1)
scan_kernel(const float* __restrict__ h0, const float* __restrict__ Whh,
            float* __restrict__ out)
{
    __shared__ __align__(16) char hbuf[2 * BUF_B];
    __shared__ __align__(8) ull mbars[2];

    const int tid  = threadIdx.x;
    const int kq   = tid & 15;
    const int g    = tid >> 4;                 // 0..31, cols 2g & 2g+1
    const int rank = blockIdx.x & (RANKS - 1);
    const int cid  = blockIdx.x >> 3;
    const int b0   = cid * BPC;
    const int gcol0 = rank * 64 + 2 * g;

    // ---- W slices for our 2 columns, k-chunk [32kq, 32kq+32)
    float w0[32], w1[32];
    {
        const float* r0 = Whh + (size_t)gcol0 * HID + kq * 32;
        const float* r1 = r0 + HID;
#pragma unroll
        for (int j4 = 0; j4 < 8; j4++) {
            float4 a = *(const float4*)(r0 + j4 * 4);
            float4 b = *(const float4*)(r1 + j4 * 4);
            w0[4*j4+0] = a.x; w0[4*j4+1] = a.y; w0[4*j4+2] = a.z; w0[4*j4+3] = a.w;
            w1[4*j4+0] = b.x; w1[4*j4+1] = b.y; w1[4*j4+2] = b.z; w1[4*j4+3] = b.w;
        }
    }

    if (tid == 0) {
        mbar_init((uint32_t)__cvta_generic_to_shared(&mbars[0]), 1);
        mbar_init((uint32_t)__cvta_generic_to_shared(&mbars[1]), 1);
    }

    // ---- preload h0 into buffer 0 (k = tid)
    {
        const int k = tid;
        float v0 = h0[(size_t)(b0 + 0) * HID + k];
        float v1 = h0[(size_t)(b0 + 1) * HID + k];
        float v2 = h0[(size_t)(b0 + 2) * HID + k];
        float v3 = h0[(size_t)(b0 + 3) * HID + k];
        char* e = hbuf + (k >> 5) * REG_STR + (k & 31) * 16;
        *(ull*)e       = pack2(v0, v1);
        *(ull*)(e + 8) = pack2(v2, v3);
    }
    __syncthreads();
    cluster_sync_();            // mbar inits + buffer0 visible cluster-wide

    const uint32_t hpb = (uint32_t)__cvta_generic_to_shared(hbuf);
    const uint32_t mbb = (uint32_t)__cvta_generic_to_shared(&mbars[0]);

    // output lanes: kq<8. col = gcol0 + (kq>>2), batch = kq&3
    const bool outl = (kq < 8);
    const int  obat = kq & 3;
    const size_t obase = outl
        ? (((size_t)(b0 + obat) * SEQ) * HID + gcol0 + (kq >> 2)) : 0;
    float xpv = outl ? out[obase] : 0.0f;

    const bool writer = (kq == 0) || (kq == 4);   // col0 / col1 entry writers

    for (int t = 0; t < SEQ; t++) {
        const int p = t & 1;
        if (t) mbar_wait(mbb + p * 8, ((t - 1) >> 1) & 1);

        const ulonglong2* hreg =
            (const ulonglong2*)(hbuf + p * BUF_B + kq * REG_STR);
        ull a01_0 = 0, a23_0 = 0, a01_1 = 0, a23_1 = 0;
#pragma unroll
        for (int j = 0; j < 32; j++) {
            ulonglong2 e = hreg[j];
            ull wd0 = dup2(w0[j]);
            ull wd1 = dup2(w1[j]);
            a01_0 = ffma2(wd0, e.x, a01_0);
            a23_0 = ffma2(wd0, e.y, a23_0);
            a01_1 = ffma2(wd1, e.x, a01_1);
            a23_1 = ffma2(wd1, e.y, a23_1);
        }

        // prefetch next step's xp while reduction/exchange runs
        float xpn = 0.0f;
        if (outl && t + 1 < SEQ) xpn = out[obase + (size_t)(t + 1) * HID];

        // allreduce over the 16 kq lanes (masks stay within the half-warp)
#pragma unroll
        for (int m = 1; m < 16; m <<= 1) {
            a01_0 = addx2(a01_0, __shfl_xor_sync(0xffffffffu, a01_0, m));
            a23_0 = addx2(a23_0, __shfl_xor_sync(0xffffffffu, a23_0, m));
            a01_1 = addx2(a01_1, __shfl_xor_sync(0xffffffffu, a01_1, m));
            a23_1 = addx2(a23_1, __shfl_xor_sync(0xffffffffu, a23_1, m));
        }

        // lane kq in [0,8): col sel = kq>>2, batch = kq&3
        float v = 0.0f;
        if (outl) {
            const ull ap = (kq < 4) ? ((obat < 2) ? a01_0 : a23_0)
                                    : ((obat < 2) ? a01_1 : a23_1);
            const float s = (obat & 1) ? f2hi(ap) : f2lo(ap);
            v = tanhf(s + xpv);
        }
        xpv = xpn;

        // gather batches 1..3 into the writer lanes (kq 0 -> col0, 4 -> col1)
        float vb1 = __shfl_down_sync(0xffffffffu, v, 1);
        float vb2 = __shfl_down_sync(0xffffffffu, v, 2);
        float vb3 = __shfl_down_sync(0xffffffffu, v, 3);

        if (t < SEQ - 1 && writer) {
            const int lc   = 2 * g + (kq >> 2);            // local col 0..63
            const int greg = 2 * rank + (lc >> 5);         // our region
            ulonglong2 e;
            e.x = pack2(v,   vb1);
            e.y = pack2(vb2, vb3);
            *(ulonglong2*)(hbuf + (1 - p) * BUF_B + greg * REG_STR +
                           (lc & 31) * 16) = e;
        }

        if (t < SEQ - 1) {
            if (tid == 0) mbar_expect_tx(mbb + (1 - p) * 8, EXCH_TX);
            __syncthreads();   // closes all reads of buf p + writer STS
            if (tid == 0) {
                asm volatile("fence.proxy.async.shared::cta;" ::: "memory");
                const uint32_t src = hpb + (uint32_t)((1 - p) * BUF_B +
                                                      2 * rank * REG_STR);
                const uint32_t lmb = mbb + (uint32_t)((1 - p) * 8);
#pragma unroll
                for (int d = 1; d < RANKS; d++)
                    cluster_bulk_copy(src, CHUNK_B, lmb, (rank + d) & (RANKS - 1));
            }
        }

        // output store off the critical path
        if (outl) out[obase + (size_t)t * HID] = v;
    }

    cluster_sync_();
}

// ---------------------------------------------------------------------------
// Launch
// ---------------------------------------------------------------------------
extern "C" void kernel_launch(void* const* d_in, const int* in_sizes, int n_in,
                              void* d_out, int out_size) {
    const float* x_in = (const float*)d_in[0];
    const float* h0   = (const float*)d_in[1];
    const float* W_ih = (const float*)d_in[2];
    const float* W_hh = (const float*)d_in[3];
    const float* b_ih = (const float*)d_in[4];
    const float* b_hh = (const float*)d_in[5];
    float* out = (float*)d_out;

    dim3 gg((BATCH * SEQ) / BM, HID / BN);
    xproj_kernel<<<gg, 256>>>(x_in, W_ih, b_ih, b_hh, out);

    scan_kernel<<<(BATCH / BPC) * RANKS, 512>>>(h0, W_hh, out);
}

// round 14
// speedup vs baseline: 2.7943x; 1.2526x over previous
#include <cuda_runtime.h>
#include <math.h>
#include <stdint.h>

typedef unsigned long long ull;

#define BATCH 64
#define SEQ   2048
#define IN_F  256
#define HID   512
#define RANKS 8     // CTAs per cluster; each owns 64 columns of W_hh
#define BPC   4     // batch rows per cluster

// 32 regions (one per kq lane) x 16 entries x 16B payload, stride 272 so the
// 32 lanes' concurrent reads are bank-conflict-free (bank = 4(kq+c) mod 32).
#define REG_STR   272
#define BUF_B     (32 * REG_STR)        // 8704 per buffer
#define CHUNK_B   1072                  // rank's 4 regions: 3*272 + 256
#define EXCH_TX   (7 * CHUNK_B)         // 7504 incoming bytes per step

// ---------------------------------------------------------------------------
// Packed f32x2 helpers
// ---------------------------------------------------------------------------
__device__ __forceinline__ ull ffma2(ull a, ull b, ull c) {
    ull d;
    asm("fma.rn.f32x2 %0, %1, %2, %3;" : "=l"(d) : "l"(a), "l"(b), "l"(c));
    return d;
}
__device__ __forceinline__ ull addx2(ull a, ull b) {
    ull d;
    asm("add.rn.f32x2 %0, %1, %2;" : "=l"(d) : "l"(a), "l"(b));
    return d;
}
__device__ __forceinline__ ull dup2(float x) {
    ull d;
    asm("mov.b64 %0, {%1, %1};" : "=l"(d) : "f"(x));
    return d;
}
__device__ __forceinline__ ull pack2(float lo, float hi) {
    ull d;
    asm("mov.b64 %0, {%1, %2};" : "=l"(d) : "f"(lo), "f"(hi));
    return d;
}
__device__ __forceinline__ float f2lo(ull v) {
    return __int_as_float((int)(unsigned int)(v & 0xffffffffULL));
}
__device__ __forceinline__ float f2hi(ull v) {
    return __int_as_float((int)(unsigned int)(v >> 32));
}
__device__ __forceinline__ ull shfl_xor64(ull v, int m) {
    float lo = f2lo(v), hi = f2hi(v);
    lo = __shfl_xor_sync(0xffffffffu, lo, m);
    hi = __shfl_xor_sync(0xffffffffu, hi, m);
    return pack2(lo, hi);
}

// ---------------------------------------------------------------------------
// mbarrier / cluster primitives (R12-identical)
// ---------------------------------------------------------------------------
__device__ __forceinline__ void mbar_init(uint32_t mbar, uint32_t cnt) {
    asm volatile("mbarrier.init.shared.b64 [%0], %1;" :: "r"(mbar), "r"(cnt) : "memory");
}
__device__ __forceinline__ void mbar_expect_tx(uint32_t mbar, uint32_t bytes) {
    asm volatile("mbarrier.arrive.expect_tx.shared.b64 _, [%0], %1;"
                 :: "r"(mbar), "r"(bytes) : "memory");
}
__device__ __forceinline__ void mbar_wait(uint32_t mbar, uint32_t parity) {
    asm volatile(
        "{\n\t"
        ".reg .pred P;\n\t"
        "WL_%=:\n\t"
        "mbarrier.try_wait.parity.acquire.cta.shared::cta.b64 P, [%0], %1, 0x989680;\n\t"
        "@P bra.uni WD_%=;\n\t"
        "bra.uni WL_%=;\n\t"
        "WD_%=:\n\t"
        "}"
        :: "r"(mbar), "r"(parity) : "memory");
}
// bulk copy: our smem chunk -> same offset in cluster rank r, signal r's mbar
__device__ __forceinline__ void cluster_bulk_copy(uint32_t local_addr, uint32_t bytes,
                                                  uint32_t local_mbar, int r) {
    uint32_t rdst, rmb;
    asm volatile("mapa.shared::cluster.u32 %0, %1, %2;" : "=r"(rdst) : "r"(local_addr), "r"(r));
    asm volatile("mapa.shared::cluster.u32 %0, %1, %2;" : "=r"(rmb) : "r"(local_mbar), "r"(r));
    asm volatile(
        "cp.async.bulk.shared::cluster.shared::cta.mbarrier::complete_tx::bytes "
        "[%0], [%1], %2, [%3];"
        :: "r"(rdst), "r"(local_addr), "r"(bytes), "r"(rmb) : "memory");
}
__device__ __forceinline__ void cluster_sync_() {
    asm volatile("barrier.cluster.arrive.aligned;" ::: "memory");
    asm volatile("barrier.cluster.wait.aligned;" ::: "memory");
}

// ---------------------------------------------------------------------------
// Kernel 1: x_proj GEMM  out[m][n] = sum_k X[m][k]*Wih[n][k] + bih[n] + bhh[n]
// ---------------------------------------------------------------------------
#define BM 128
#define BN 64
#define BK 32
#define ASP 130

__global__ __launch_bounds__(256) void xproj_kernel(
    const float* __restrict__ X, const float* __restrict__ Wih,
    const float* __restrict__ bih, const float* __restrict__ bhh,
    float* __restrict__ out)
{
    __shared__ float As[BK][ASP];
    __shared__ float Ws[BK][BN];

    const int tid = threadIdx.x;
    const int m0 = blockIdx.x * BM;
    const int n0 = blockIdx.y * BN;
    const int tx = tid & 15;
    const int ty = tid >> 4;

    ull acc[4][4];
#pragma unroll
    for (int r = 0; r < 4; r++)
#pragma unroll
        for (int c = 0; c < 4; c++) acc[r][c] = 0ULL;

    for (int k0 = 0; k0 < IN_F; k0 += BK) {
#pragma unroll
        for (int i = 0; i < 4; i++) {
            int idx = tid + i * 256;
            int m = idx >> 3;
            int k4 = idx & 7;
            float4 v = *(const float4*)(X + (size_t)(m0 + m) * IN_F + k0 + k4 * 4);
            As[k4 * 4 + 0][m] = v.x;
            As[k4 * 4 + 1][m] = v.y;
            As[k4 * 4 + 2][m] = v.z;
            As[k4 * 4 + 3][m] = v.w;
        }
#pragma unroll
        for (int i = 0; i < 2; i++) {
            int idx = tid + i * 256;
            int n = idx >> 3;
            int k4 = idx & 7;
            float4 v = *(const float4*)(Wih + (size_t)(n0 + n) * IN_F + k0 + k4 * 4);
            Ws[k4 * 4 + 0][n] = v.x;
            Ws[k4 * 4 + 1][n] = v.y;
            Ws[k4 * 4 + 2][n] = v.z;
            Ws[k4 * 4 + 3][n] = v.w;
        }
        __syncthreads();

#pragma unroll
        for (int k = 0; k < BK; k++) {
            ull ap[4];
#pragma unroll
            for (int r = 0; r < 4; r++)
                ap[r] = *(const ull*)&As[k][ty * 8 + 2 * r];
            float4 wv = *(const float4*)&Ws[k][tx * 4];
            ull wd0 = dup2(wv.x), wd1 = dup2(wv.y);
            ull wd2 = dup2(wv.z), wd3 = dup2(wv.w);
#pragma unroll
            for (int r = 0; r < 4; r++) {
                acc[r][0] = ffma2(ap[r], wd0, acc[r][0]);
                acc[r][1] = ffma2(ap[r], wd1, acc[r][1]);
                acc[r][2] = ffma2(ap[r], wd2, acc[r][2]);
                acc[r][3] = ffma2(ap[r], wd3, acc[r][3]);
            }
        }
        __syncthreads();
    }

    float bsum[4];
#pragma unroll
    for (int c = 0; c < 4; c++) {
        int n = n0 + tx * 4 + c;
        bsum[c] = bih[n] + bhh[n];
    }
#pragma unroll
    for (int r = 0; r < 4; r++) {
        size_t mlo = (size_t)(m0 + ty * 8 + 2 * r);
        float4 lo4, hi4;
        lo4.x = f2lo(acc[r][0]) + bsum[0]; lo4.y = f2lo(acc[r][1]) + bsum[1];
        lo4.z = f2lo(acc[r][2]) + bsum[2]; lo4.w = f2lo(acc[r][3]) + bsum[3];
        hi4.x = f2hi(acc[r][0]) + bsum[0]; hi4.y = f2hi(acc[r][1]) + bsum[1];
        hi4.z = f2hi(acc[r][2]) + bsum[2]; hi4.w = f2hi(acc[r][3]) + bsum[3];
        *(float4*)(out + mlo * HID + n0 + tx * 4)       = lo4;
        *(float4*)(out + (mlo + 1) * HID + n0 + tx * 4) = hi4;
    }
}

// ---------------------------------------------------------------------------
// Kernel 2: cluster scan — R12 exchange protocol (single mbar per buffer;
// expect_tx -> __syncthreads -> fence -> 7 bulk copies), compute remapped to
// 4 columns/thread: crossbar traffic halves again (16 LDS.128/thread), and
// the reduce is a warp-local value-splitting butterfly (9 shfl.64).
//
// 16 clusters x 8 CTAs; cluster owns 4 batch rows, CTA rank owns 64 cols.
// 512 threads = 16 warps; warp g owns cols [4g, 4g+4); lane kq in [0,32) is
// the k-chunk [16kq, 16kq+16).
//
// h smem: 2 buffers x 32 regions x 16 entries x 16B (stride 272). Entry c of
// region r = ((h_b0,h_b1),(h_b2,h_b3)) for k = r*16+c. Lane kq reads region
// kq entries 0..15: bank = 4(kq+c) mod 32 -> conflict-free in every phase.
// Per 16B entry each thread does 16 MACs (4 cols x 4 batches).
//
// Butterfly (value-splitting, 8 accs -> 1): xor16 keeps 2 cols (4 shfl),
// xor8 keeps 1 col (2), xor4 keeps 1 batch-pair (1), xor2 (1), xor1 (1).
// Final lane map: col c = (lane>>3)&3, batch-pair bp = (lane>>2)&1, packed
// value = batches (2bp, 2bp+1). Output lanes: (lane&2)==0, batch = 2bp +
// (lane&1). Writers: (lane&7)==0 gather b1..b3 via shfl_down 1/4/5.
//
// Rank r owns regions [4r, 4r+4); exchange chunk = contiguous 1072B.
// ---------------------------------------------------------------------------
__global__ void __cluster_dims__(RANKS, 1, 1) __launch_bounds__(512, 1)
scan_kernel(const float* __restrict__ h0, const float* __restrict__ Whh,
            float* __restrict__ out)
{
    __shared__ __align__(16) char hbuf[2 * BUF_B];
    __shared__ __align__(8) ull mbars[2];

    const int tid  = threadIdx.x;
    const int lane = tid & 31;                 // = kq (k-chunk index)
    const int grp  = tid >> 5;                 // warp id = column group
    const int rank = blockIdx.x & (RANKS - 1);
    const int cid  = blockIdx.x >> 3;
    const int b0   = cid * BPC;
    const int gcol0 = rank * 64 + 4 * grp;     // first of our 4 columns

    // ---- W slices: 4 cols x 16 ks
    float w[4][16];
#pragma unroll
    for (int c = 0; c < 4; c++) {
        const float* wr = Whh + (size_t)(gcol0 + c) * HID + lane * 16;
#pragma unroll
        for (int j4 = 0; j4 < 4; j4++) {
            float4 a = *(const float4*)(wr + j4 * 4);
            w[c][4*j4+0] = a.x; w[c][4*j4+1] = a.y;
            w[c][4*j4+2] = a.z; w[c][4*j4+3] = a.w;
        }
    }

    if (tid == 0) {
        mbar_init((uint32_t)__cvta_generic_to_shared(&mbars[0]), 1);
        mbar_init((uint32_t)__cvta_generic_to_shared(&mbars[1]), 1);
    }

    // ---- preload h0 into buffer 0 (k = tid)
    {
        const int k = tid;
        float v0 = h0[(size_t)(b0 + 0) * HID + k];
        float v1 = h0[(size_t)(b0 + 1) * HID + k];
        float v2 = h0[(size_t)(b0 + 2) * HID + k];
        float v3 = h0[(size_t)(b0 + 3) * HID + k];
        char* e = hbuf + (k >> 4) * REG_STR + (k & 15) * 16;
        *(ull*)e       = pack2(v0, v1);
        *(ull*)(e + 8) = pack2(v2, v3);
    }
    __syncthreads();
    cluster_sync_();            // mbar inits + buffer0 visible cluster-wide

    const uint32_t hpb = (uint32_t)__cvta_generic_to_shared(hbuf);
    const uint32_t mbb = (uint32_t)__cvta_generic_to_shared(&mbars[0]);

    // final-lane roles
    const int  fcol = (lane >> 3) & 3;              // col within group
    const int  fbp  = (lane >> 2) & 1;              // batch pair
    const bool outl = (lane & 2) == 0;
    const int  obat = 2 * fbp + (lane & 1);
    const size_t obase = outl
        ? (((size_t)(b0 + obat) * SEQ) * HID + gcol0 + fcol) : 0;
    float xpv = outl ? out[obase] : 0.0f;

    const bool writer = (lane & 7) == 0;            // lanes 0,8,16,24

    for (int t = 0; t < SEQ; t++) {
        const int p = t & 1;
        if (t) mbar_wait(mbb + p * 8, ((t - 1) >> 1) & 1);

        const ulonglong2* hreg =
            (const ulonglong2*)(hbuf + p * BUF_B + lane * REG_STR);
        ull a01[4] = {0, 0, 0, 0};
        ull a23[4] = {0, 0, 0, 0};
#pragma unroll
        for (int j = 0; j < 16; j++) {
            ulonglong2 e = hreg[j];
#pragma unroll
            for (int c = 0; c < 4; c++) {
                ull wd = dup2(w[c][j]);
                a01[c] = ffma2(wd, e.x, a01[c]);
                a23[c] = ffma2(wd, e.y, a23[c]);
            }
        }

        // prefetch next step's xp while reduction/exchange runs
        float xpn = 0.0f;
        if (outl && t + 1 < SEQ) xpn = out[obase + (size_t)(t + 1) * HID];

        // ---- value-splitting butterfly over the full warp
        const bool hi16 = (lane & 16) != 0;
        // xor16: keep cols {0,1} (lo half) or {2,3} (hi half)
        ull s0 = hi16 ? a01[2] : a01[0];
        ull s1 = hi16 ? a23[2] : a23[0];
        ull s2 = hi16 ? a01[3] : a01[1];
        ull s3 = hi16 ? a23[3] : a23[1];
        s0 = addx2(s0, shfl_xor64(hi16 ? a01[0] : a01[2], 16));
        s1 = addx2(s1, shfl_xor64(hi16 ? a23[0] : a23[2], 16));
        s2 = addx2(s2, shfl_xor64(hi16 ? a01[1] : a01[3], 16));
        s3 = addx2(s3, shfl_xor64(hi16 ? a23[1] : a23[3], 16));
        // xor8: keep one col
        const bool hi8 = (lane & 8) != 0;
        ull t0 = hi8 ? s2 : s0;
        ull t1 = hi8 ? s3 : s1;
        t0 = addx2(t0, shfl_xor64(hi8 ? s0 : s2, 8));
        t1 = addx2(t1, shfl_xor64(hi8 ? s1 : s3, 8));
        // xor4: keep one batch pair
        const bool hi4 = (lane & 4) != 0;
        ull r = hi4 ? t1 : t0;
        r = addx2(r, shfl_xor64(hi4 ? t0 : t1, 4));
        // xor2, xor1: plain
        r = addx2(r, shfl_xor64(r, 2));
        r = addx2(r, shfl_xor64(r, 1));

        float v = 0.0f;
        if (outl) {
            const float s = (lane & 1) ? f2hi(r) : f2lo(r);
            v = tanhf(s + xpv);
        }
        xpv = xpn;

        // writers gather batches 1..3 (lanes +1, +4, +5 of same col)
        float vb1 = __shfl_down_sync(0xffffffffu, v, 1);
        float vb2 = __shfl_down_sync(0xffffffffu, v, 4);
        float vb3 = __shfl_down_sync(0xffffffffu, v, 5);

        if (t < SEQ - 1 && writer) {
            const int lc = 4 * grp + fcol;             // local col 0..63
            ulonglong2 e;
            e.x = pack2(v,   vb1);
            e.y = pack2(vb2, vb3);
            *(ulonglong2*)(hbuf + (1 - p) * BUF_B +
                           (4 * rank + (lc >> 4)) * REG_STR +
                           (lc & 15) * 16) = e;
        }

        if (t < SEQ - 1) {
            if (tid == 0) mbar_expect_tx(mbb + (1 - p) * 8, EXCH_TX);
            __syncthreads();   // closes all reads of buf p + writer STS
            // warps 1..7 each send our chunk to one peer
            if (grp >= 1 && grp <= 7 && lane == 0) {
                asm volatile("fence.proxy.async.shared::cta;" ::: "memory");
                const uint32_t src = hpb + (uint32_t)((1 - p) * BUF_B +
                                                      4 * rank * REG_STR);
                const uint32_t lmb = mbb + (uint32_t)((1 - p) * 8);
                cluster_bulk_copy(src, CHUNK_B, lmb, (rank + grp) & (RANKS - 1));
            }
        }

        // output store off the critical path
        if (outl) out[obase + (size_t)t * HID] = v;
    }

    cluster_sync_();
}

// ---------------------------------------------------------------------------
// Launch
// ---------------------------------------------------------------------------
extern "C" void kernel_launch(void* const* d_in, const int* in_sizes, int n_in,
                              void* d_out, int out_size) {
    const float* x_in = (const float*)d_in[0];
    const float* h0   = (const float*)d_in[1];
    const float* W_ih = (const float*)d_in[2];
    const float* W_hh = (const float*)d_in[3];
    const float* b_ih = (const float*)d_in[4];
    const float* b_hh = (const float*)d_in[5];
    float* out = (float*)d_out;

    dim3 gg((BATCH * SEQ) / BM, HID / BN);
    xproj_kernel<<<gg, 256>>>(x_in, W_ih, b_ih, b_hh, out);

    scan_kernel<<<(BATCH / BPC) * RANKS, 512>>>(h0, W_hh, out);
}